// round 3
// baseline (speedup 1.0000x reference)
#include <cuda_runtime.h>
#include <cuda_bf16.h>

// Problem constants (fixed by the dataset)
#define T 12
#define C 32
#define NMAX 100000

// LUT over scalar aggregate value a
#define LUT_ROWS 8192
#define A_RANGE  12.0f

// Scratch (no cudaMalloc allowed)
__device__ float g_deg[NMAX];
__device__ float g_dinv[NMAX];
__device__ __align__(16) float g_xs[NMAX * T];       // dinv[n] * x[n,t]
__device__ __align__(16) float g_aggraw[NMAX * T];   // sum_e w * xs[src]
__device__ __align__(16) float g_lut[(LUT_ROWS + 1) * C];

// Fused per-channel coefficients
__device__ float g_az[C];   // lw_z[:, :C] @ w_z[0]
__device__ float g_bz[C];   // lw_z[:, :C] @ b_z + lb_z
__device__ float g_ah[C];   // lw_h[:, :C] @ w_h[0]
__device__ float g_bh[C];   // lw_h[:, :C] @ b_h + lb_h
__device__ float g_hw[C];   // head_w
__device__ float g_wp[T];   // softmax(att)
__device__ float g_hb;      // head_b

__device__ __forceinline__ float ex2f(float x) {
    float y;
    asm("ex2.approx.f32 %0, %1;" : "=f"(y) : "f"(x));
    return y;
}
// Accurate (~1e-7) tanh/sigmoid built on ex2 (MUFU EX2 is ~2^-22 accurate)
__device__ __forceinline__ float tanh_acc(float v) {
    v = fminf(fmaxf(v, -20.0f), 20.0f);
    float e = ex2f(-2.885390082f * v);   // exp(-2v)
    return (1.0f - e) / (1.0f + e);
}
__device__ __forceinline__ float sigmoid_acc(float v) {
    v = fminf(fmaxf(v, -30.0f), 30.0f);
    float e = ex2f(-1.442695041f * v);   // exp(-v)
    return 1.0f / (1.0f + e);
}

// ---------------------------------------------------------------------------
// Stage 0a: fuse weights (1 block, 32 threads)
// ---------------------------------------------------------------------------
__global__ void precompute_kernel(
    const float* __restrict__ wz, const float* __restrict__ bz,
    const float* __restrict__ wh, const float* __restrict__ bh,
    const float* __restrict__ lwz, const float* __restrict__ lbz,
    const float* __restrict__ lwh, const float* __restrict__ lbh,
    const float* __restrict__ att,
    const float* __restrict__ head_w, const float* __restrict__ head_b)
{
    int c = threadIdx.x;
    if (c < C) {
        float az = 0.f, bzs = 0.f, ah = 0.f, bhs = 0.f;
        #pragma unroll
        for (int k = 0; k < C; k++) {
            float lz = lwz[c * 2 * C + k];
            float lh = lwh[c * 2 * C + k];
            az  = fmaf(lz, wz[k], az);
            bzs = fmaf(lz, bz[k], bzs);
            ah  = fmaf(lh, wh[k], ah);
            bhs = fmaf(lh, bh[k], bhs);
        }
        g_az[c] = az;
        g_bz[c] = bzs + lbz[c];
        g_ah[c] = ah;
        g_bh[c] = bhs + lbh[c];
        g_hw[c] = head_w[c];
    }
    if (c == 0) {
        float m = -1e30f;
        for (int t = 0; t < T; t++) m = fmaxf(m, att[t]);
        float ex[T]; float s = 0.f;
        for (int t = 0; t < T; t++) { ex[t] = ex2f(1.442695041f * (att[t] - m)); s += ex[t]; }
        float inv = 1.0f / s;
        for (int t = 0; t < T; t++) g_wp[t] = ex[t] * inv;
        g_hb = head_b[0];
    }
}

// ---------------------------------------------------------------------------
// Stage 0b: build LUT  g[r][c] = (1 - sigmoid(a*az+bz)) * tanh(a*ah+bh)
// ---------------------------------------------------------------------------
__global__ void lut_kernel() {
    int i = blockIdx.x * blockDim.x + threadIdx.x;
    if (i >= (LUT_ROWS + 1) * C) return;
    int r = i >> 5;
    int c = i & 31;
    float a = -A_RANGE + (2.0f * A_RANGE / LUT_ROWS) * (float)r;
    float z = sigmoid_acc(fmaf(a, g_az[c], g_bz[c]));
    float h = tanh_acc(fmaf(a, g_ah[c], g_bh[c]));
    g_lut[i] = (1.0f - z) * h;
}

// ---------------------------------------------------------------------------
// Stage 1: init deg = 1 (self-loop), zero agg_raw (float4 stores)
// ---------------------------------------------------------------------------
__global__ void init_kernel(int n) {
    int i = blockIdx.x * blockDim.x + threadIdx.x;
    int q = (n * T) >> 2;   // 300000 float4s
    if (i < q)
        ((float4*)g_aggraw)[i] = make_float4(0.f, 0.f, 0.f, 0.f);
    if (i < n) g_deg[i] = 1.0f;
}

// ---------------------------------------------------------------------------
// Stage 2: degree scatter-add (atomicAdd w/ dead return -> REDG)
// ---------------------------------------------------------------------------
__global__ void deg_kernel(const int* __restrict__ ei,
                           const float* __restrict__ ew, int e) {
    int i = blockIdx.x * blockDim.x + threadIdx.x;
    if (i < e) {
        int d = __ldg(ei + e + i);          // destinations
        atomicAdd(&g_deg[d], __ldg(ew + i));
    }
}

// ---------------------------------------------------------------------------
// Stage 3: dinv = rsqrt(deg); xs = dinv * x
// ---------------------------------------------------------------------------
__global__ void xs_kernel(const float* __restrict__ x, int n) {
    int i = blockIdx.x * blockDim.x + threadIdx.x;
    if (i >= n) return;
    float dv = rsqrtf(g_deg[i]);   // deg >= 1 always
    g_dinv[i] = dv;
    const float4* xr = (const float4*)(x + (size_t)i * T);
    float4* o = (float4*)(g_xs + (size_t)i * T);
    #pragma unroll
    for (int k = 0; k < 3; k++) {
        float4 v = xr[k];
        v.x *= dv; v.y *= dv; v.z *= dv; v.w *= dv;
        o[k] = v;
    }
}

// ---------------------------------------------------------------------------
// Stage 4: edge aggregation: agg_raw[d,:] += w * xs[s,:]
// Grid-stride, 2 edges per iteration for MLP; v4 REDG (3 per edge).
// ---------------------------------------------------------------------------
__device__ __forceinline__ void edge_one(int s, int d, float w) {
    const float4* xr = (const float4*)(g_xs + (size_t)s * T);
    float* dst = g_aggraw + (size_t)d * T;
    #pragma unroll
    for (int k = 0; k < 3; k++) {
        float4 v = __ldg(xr + k);
        float a = v.x * w, b = v.y * w, c = v.z * w, q = v.w * w;
        asm volatile("red.global.add.v4.f32 [%0], {%1,%2,%3,%4};"
                     :: "l"(dst + 4 * k), "f"(a), "f"(b), "f"(c), "f"(q)
                     : "memory");
    }
}

__global__ void edge_agg_kernel(const int* __restrict__ ei,
                                const float* __restrict__ ew, int e) {
    int i0 = 2 * (blockIdx.x * blockDim.x + threadIdx.x);
    if (i0 + 1 < e) {
        int s0 = __ldg(ei + i0),     s1 = __ldg(ei + i0 + 1);
        int d0 = __ldg(ei + e + i0), d1 = __ldg(ei + e + i0 + 1);
        float w0 = __ldg(ew + i0),   w1 = __ldg(ew + i0 + 1);
        edge_one(s0, d0, w0);
        edge_one(s1, d1, w1);
    } else if (i0 < e) {
        edge_one(__ldg(ei + i0), __ldg(ei + e + i0), __ldg(ew + i0));
    }
}

// ---------------------------------------------------------------------------
// Stage 5: warp-per-node. lane = channel.
//   a_t = dinv * (agg_raw + xs); acc_c = sum_t wp_t * lerp(LUT, a_t)[c]
//   out = hb + sum_c hw_c * relu(acc_c)
// ---------------------------------------------------------------------------
__global__ void node_kernel(float* __restrict__ out, int n) {
    int gtid = blockIdx.x * blockDim.x + threadIdx.x;
    int i = gtid >> 5;        // node
    int lane = gtid & 31;     // channel
    if (i >= n) return;

    float hw = g_hw[lane];
    float wp[T];
    #pragma unroll
    for (int t = 0; t < T; t++) wp[t] = g_wp[t];

    float dv = g_dinv[i];
    const float4* ag = (const float4*)(g_aggraw + (size_t)i * T);
    const float4* xp = (const float4*)(g_xs + (size_t)i * T);
    float a[T];
    #pragma unroll
    for (int k = 0; k < 3; k++) {
        float4 u = ag[k];
        float4 v = xp[k];
        a[4 * k + 0] = dv * (u.x + v.x);
        a[4 * k + 1] = dv * (u.y + v.y);
        a[4 * k + 2] = dv * (u.z + v.z);
        a[4 * k + 3] = dv * (u.w + v.w);
    }

    const float invD = (float)LUT_ROWS / (2.0f * A_RANGE);
    const float pmax = (float)LUT_ROWS - 0.001f;

    float acc = 0.0f;
    #pragma unroll
    for (int t = 0; t < T; t++) {
        float pos = fmaf(a[t], invD, A_RANGE * invD);
        pos = fminf(fmaxf(pos, 0.0f), pmax);
        int idx = (int)pos;
        float f = pos - (float)idx;
        const float* row = g_lut + idx * C + lane;
        float r0 = __ldg(row);
        float r1 = __ldg(row + C);
        float w1 = wp[t] * f;
        float w0 = wp[t] - w1;
        acc = fmaf(r0, w0, fmaf(r1, w1, acc));
    }

    float v = fmaxf(acc, 0.0f) * hw;
    #pragma unroll
    for (int off = 16; off > 0; off >>= 1)
        v += __shfl_xor_sync(0xFFFFFFFFu, v, off);
    if (lane == 0) out[i] = v + g_hb;
}

// ---------------------------------------------------------------------------
extern "C" void kernel_launch(void* const* d_in, const int* in_sizes, int n_in,
                              void* d_out, int out_size) {
    const float* x      = (const float*)d_in[0];
    const int*   ei     = (const int*)  d_in[1];
    const float* ew     = (const float*)d_in[2];
    const float* wz     = (const float*)d_in[3];
    const float* bz     = (const float*)d_in[4];
    // d_in[5], d_in[6]: w_r, b_r (unused: reset gate multiplies H=0)
    const float* wh     = (const float*)d_in[7];
    const float* bh     = (const float*)d_in[8];
    const float* lwz    = (const float*)d_in[9];
    const float* lbz    = (const float*)d_in[10];
    // d_in[11], d_in[12]: lw_r, lb_r (unused)
    const float* lwh    = (const float*)d_in[13];
    const float* lbh    = (const float*)d_in[14];
    const float* att    = (const float*)d_in[15];
    const float* head_w = (const float*)d_in[16];
    const float* head_b = (const float*)d_in[17];
    float* out = (float*)d_out;

    int n = in_sizes[0] / T;   // 100000
    int e = in_sizes[2];       // 3.2M

    const int B = 256;
    precompute_kernel<<<1, 32>>>(wz, bz, wh, bh, lwz, lbz, lwh, lbh,
                                 att, head_w, head_b);
    lut_kernel<<<((LUT_ROWS + 1) * C + B - 1) / B, B>>>();
    init_kernel<<<(n * T / 4 + B - 1) / B, B>>>(n);
    deg_kernel<<<(e + B - 1) / B, B>>>(ei, ew, e);
    xs_kernel<<<(n + B - 1) / B, B>>>(x, n);
    edge_agg_kernel<<<((e + 1) / 2 + B - 1) / B, B>>>(ei, ew, e);
    node_kernel<<<(n * 32 + B - 1) / B, B>>>(out, n);
}